// round 4
// baseline (speedup 1.0000x reference)
#include <cuda_runtime.h>

typedef unsigned long long u64;

// Scratch (device globals; no allocations allowed).
__device__ __align__(16) float g_Gp[4 * 8 * 65536];   // gram partials (K-split 4)
__device__ __align__(16) float g_G [8 * 65536];       // G[b*4+q] 256x256
__device__ __align__(16) float g_T [8 * 1024 * 256];  // T[b*4+a] 1024x256
__device__ __align__(16) float g_Mp[4 * 8 * 65536];   // fold partials (K-split 4)
__device__ __align__(16) float g_M [8 * 65536];       // M[b*4+a] 256x256

__device__ __forceinline__ u64 fma2(u64 a, u64 b, u64 c) {
    u64 d;
    asm("fma.rn.f32x2 %0, %1, %2, %3;" : "=l"(d) : "l"(a), "l"(b), "l"(c));
    return d;
}
__device__ __forceinline__ float lo_f(u64 v) { return __uint_as_float((unsigned)v); }
__device__ __forceinline__ float hi_f(u64 v) { return __uint_as_float((unsigned)(v >> 32)); }

// 64x64 tile, BK=32, 256 threads, 4m x 4n micro-tile (m packed in 2 pairs).
constexpr int BM = 64, BN = 64, BK = 32;
constexpr int SA  = 68;   // As row stride (floats): 64 + 4 pad (16B-aligned rows)
constexpr int SBD = 132;  // Bs row stride (floats): 2*64 duplicated + 4 pad

// C[m,n] += A(.)B with As[k][m], Bs_dup[k][2n].
// TRANS_A: A global is [K x M] (rows read directly); else [M x K] (transposed at fill).
template <bool TRANS_A>
__device__ __forceinline__ void gemm_core(
    const float* __restrict__ A, int lda,
    const float* __restrict__ B, int ldb,
    float* __restrict__ C, int ldc,
    int kbeg, int kend, int m0, int n0)
{
    __shared__ __align__(16) float As[BK * SA];
    __shared__ __align__(16) float Bs[BK * SBD];

    const int tid = threadIdx.x;
    const int tx = tid & 15;      // n sub-tile (4 cols at tx*4)
    const int ty = tid >> 4;      // m sub-tile (4 rows at ty*4, 2 packed pairs)
    // loader indices
    const int a_c4 = tid & 7,  a_r  = tid >> 3;   // NN A: 8 float4 across k, 32 m-rows
    const int t_c4 = tid & 15, t_kr = tid >> 4;   // TN A: 16 float4 across m, 16 k-rows
    const int b_c4 = tid & 15, b_kr = tid >> 4;   // B   : 16 float4 across n, 16 k-rows

    u64 acc[2][4] = {};

    for (int k0 = kbeg; k0 < kend; k0 += BK) {
        if (TRANS_A) {
            #pragma unroll
            for (int p = 0; p < 2; p++) {
                int k = t_kr + p * 16;
                float4 v = *reinterpret_cast<const float4*>(
                    &A[(size_t)(k0 + k) * lda + m0 + t_c4 * 4]);
                *reinterpret_cast<float4*>(&As[k * SA + t_c4 * 4]) = v;
            }
        } else {
            #pragma unroll
            for (int p = 0; p < 2; p++) {
                int m = a_r + p * 32;
                float4 v = *reinterpret_cast<const float4*>(
                    &A[(size_t)(m0 + m) * lda + k0 + a_c4 * 4]);
                As[(a_c4 * 4 + 0) * SA + m] = v.x;
                As[(a_c4 * 4 + 1) * SA + m] = v.y;
                As[(a_c4 * 4 + 2) * SA + m] = v.z;
                As[(a_c4 * 4 + 3) * SA + m] = v.w;
            }
        }
        #pragma unroll
        for (int p = 0; p < 2; p++) {
            int k = b_kr + p * 16;
            float4 v = *reinterpret_cast<const float4*>(
                &B[(size_t)(k0 + k) * ldb + n0 + b_c4 * 4]);
            float2* d = reinterpret_cast<float2*>(&Bs[k * SBD + b_c4 * 8]);
            d[0] = make_float2(v.x, v.x);
            d[1] = make_float2(v.y, v.y);
            d[2] = make_float2(v.z, v.z);
            d[3] = make_float2(v.w, v.w);
        }
        __syncthreads();

        #pragma unroll
        for (int kk = 0; kk < BK; kk++) {
            ulonglong2 av  = *reinterpret_cast<const ulonglong2*>(&As[kk * SA + ty * 4]);
            ulonglong2 bv0 = *reinterpret_cast<const ulonglong2*>(&Bs[kk * SBD + tx * 8]);
            ulonglong2 bv1 = *reinterpret_cast<const ulonglong2*>(&Bs[kk * SBD + tx * 8 + 4]);
            u64 a[2] = {av.x, av.y};
            u64 b[4] = {bv0.x, bv0.y, bv1.x, bv1.y};
            #pragma unroll
            for (int i = 0; i < 2; i++)
                #pragma unroll
                for (int j = 0; j < 4; j++)
                    acc[i][j] = fma2(a[i], b[j], acc[i][j]);
        }
        __syncthreads();
    }

    #pragma unroll
    for (int i = 0; i < 2; i++) {
        int mrow = m0 + ty * 4 + 2 * i;
        float4 o0, o1;
        o0.x = lo_f(acc[i][0]); o0.y = lo_f(acc[i][1]);
        o0.z = lo_f(acc[i][2]); o0.w = lo_f(acc[i][3]);
        o1.x = hi_f(acc[i][0]); o1.y = hi_f(acc[i][1]);
        o1.z = hi_f(acc[i][2]); o1.w = hi_f(acc[i][3]);
        *reinterpret_cast<float4*>(&C[(size_t)mrow * ldc + n0 + tx * 4]) = o0;
        *reinterpret_cast<float4*>(&C[(size_t)(mrow + 1) * ldc + n0 + tx * 4]) = o1;
    }
}

// Stage A: G[b,q] = X^T X  (K=2048, split 4) — grid (16, 8, 4)
__global__ void __launch_bounds__(256) k_gram(const float* __restrict__ hidden)
{
    const int pair = blockIdx.y;                  // b*4 + q
    const int b = pair >> 2, q = pair & 3;
    const float* X = hidden + (size_t)b * 2048 * 1024 + q * 256;
    float* C = g_Gp + ((size_t)blockIdx.z * 8 + pair) * 65536;
    const int m0 = (blockIdx.x >> 2) * BM, n0 = (blockIdx.x & 3) * BN;
    const int kbeg = blockIdx.z * 512;
    gemm_core<true>(X, 1024, X, 1024, C, 256, kbeg, kbeg + 512, m0, n0);
}

__global__ void __launch_bounds__(256) k_gred()
{
    const int i = blockIdx.x * 256 + threadIdx.x;     // 131072 float4 total
    const float4* P = reinterpret_cast<const float4*>(g_Gp);
    float4 s = P[i];
    float4 t1 = P[i + 131072], t2 = P[i + 2 * 131072], t3 = P[i + 3 * 131072];
    s.x += t1.x + t2.x + t3.x;
    s.y += t1.y + t2.y + t3.y;
    s.z += t1.z + t2.z + t3.z;
    s.w += t1.w + t2.w + t3.w;
    reinterpret_cast<float4*>(g_G)[i] = s;
}

// Stage B1: T[b,a][q*256+f, g] = G[b,q] @ C_{a,q} — grid (16, 32)
__global__ void __launch_bounds__(256) k_gc(const float* __restrict__ comb)
{
    const int combo = blockIdx.y;                 // ((b*4+a)*4 + q)
    const int q = combo & 3, a = (combo >> 2) & 3, b = combo >> 4;
    const float* A = g_G + (size_t)(b * 4 + q) * 65536;
    const float* B = comb + ((size_t)a * 1024 + q * 256) * 256;
    float* C = g_T + ((size_t)(b * 4 + a) * 1024 + q * 256) * 256;
    const int m0 = (blockIdx.x >> 2) * BM, n0 = (blockIdx.x & 3) * BN;
    gemm_core<false>(A, 256, B, 256, C, 256, 0, 256, m0, n0);
}

// Stage B2: M[b,a] = queries[a] (256x1024) @ T[b,a] (1024x256)  (K split 4)
// grid (16, 8, 4)
__global__ void __launch_bounds__(256) k_fold(const float* __restrict__ queries)
{
    const int combo = blockIdx.y;                 // b*4 + a
    const int a = combo & 3;
    const float* A = queries + (size_t)a * 256 * 1024;
    const float* B = g_T + (size_t)combo * 1024 * 256;
    float* C = g_Mp + ((size_t)blockIdx.z * 8 + combo) * 65536;
    const int m0 = (blockIdx.x >> 2) * BM, n0 = (blockIdx.x & 3) * BN;
    const int kbeg = blockIdx.z * 256;
    gemm_core<false>(A, 1024, B, 256, C, 256, kbeg, kbeg + 256, m0, n0);
}

__global__ void __launch_bounds__(256) k_mred()
{
    const int i = blockIdx.x * 256 + threadIdx.x;     // 131072 float4 total
    const float4* P = reinterpret_cast<const float4*>(g_Mp);
    float4 s = P[i];
    float4 t1 = P[i + 131072], t2 = P[i + 2 * 131072], t3 = P[i + 3 * 131072];
    s.x += t1.x + t2.x + t3.x;
    s.y += t1.y + t2.y + t3.y;
    s.z += t1.z + t2.z + t3.z;
    s.w += t1.w + t2.w + t3.w;
    reinterpret_cast<float4*>(g_M)[i] = s;
}

// Stage C: out[b,:,a*256:(a+1)*256] = hidden[b,:,a*256:(a+1)*256] @ M[b,a]
// grid (128, 8)
__global__ void __launch_bounds__(256) k_out(const float* __restrict__ hidden,
                                             float* __restrict__ out)
{
    const int combo = blockIdx.y;                 // b*4 + a
    const int b = combo >> 2, a = combo & 3;
    const float* A = hidden + (size_t)b * 2048 * 1024 + a * 256;
    const float* B = g_M + (size_t)combo * 65536;
    float* C = out + (size_t)b * 2048 * 1024 + a * 256;
    const int m0 = (blockIdx.x >> 2) * BM, n0 = (blockIdx.x & 3) * BN;
    gemm_core<false>(A, 1024, B, 256, C, 1024, 0, 256, m0, n0);
}

extern "C" void kernel_launch(void* const* d_in, const int* in_sizes, int n_in,
                              void* d_out, int out_size)
{
    const float* hidden  = (const float*)d_in[0];   // [2, 2048, 1024]
    const float* queries = (const float*)d_in[1];   // [4, 256, 1024]
    const float* comb    = (const float*)d_in[2];   // [4, 1024, 256]
    float* out = (float*)d_out;                     // [2, 2048, 1024]

    dim3 blk(256);
    k_gram<<<dim3(16, 8, 4), blk>>>(hidden);
    k_gred<<<512, 256>>>();
    k_gc  <<<dim3(16, 32), blk>>>(comb);
    k_fold<<<dim3(16, 8, 4), blk>>>(queries);
    k_mred<<<512, 256>>>();
    k_out <<<dim3(128, 8), blk>>>(hidden, out);
}

// round 5
// speedup vs baseline: 2.6480x; 2.6480x over previous
#include <cuda_runtime.h>

typedef unsigned long long u64;

// Scratch (device globals; no allocations allowed).
__device__ __align__(16) float g_Gp[8 * 8 * 65536];     // gram partials (K-split 8)
__device__ __align__(16) float g_G [8 * 65536];         // G[b*4+q] 256x256 (symmetric)
__device__ __align__(16) float g_Tp[2 * 8 * 1024 * 256];// gc partials (K-split 2)
__device__ __align__(16) float g_T [8 * 1024 * 256];    // T[b*4+a] 1024x256
__device__ __align__(16) float g_Mp[8 * 8 * 65536];     // fold partials (K-split 8)
__device__ __align__(16) float g_M [8 * 65536];         // M[b*4+a] 256x256

__device__ __forceinline__ u64 fma2(u64 a, u64 b, u64 c) {
    u64 d;
    asm("fma.rn.f32x2 %0, %1, %2, %3;" : "=l"(d) : "l"(a), "l"(b), "l"(c));
    return d;
}
__device__ __forceinline__ u64 dup2(float x) {
    u64 d;
    asm("mov.b64 %0, {%1, %1};" : "=l"(d) : "f"(x));
    return d;
}
__device__ __forceinline__ float lo_f(u64 v) { return __uint_as_float((unsigned)v); }
__device__ __forceinline__ float hi_f(u64 v) { return __uint_as_float((unsigned)(v >> 32)); }

// 128x128 tile, BK=32, 256 threads, 8m x 8n micro-tile.
// As[k][m], Bs[k][n] both k-major, un-duplicated (minimal LDS bytes).
constexpr int BM = 128, BN = 128, BK = 32;
constexpr int SL = 132;   // row stride in floats (132*4=528 = 16*33, 16B-aligned rows)

// C[m,n] += sum_k A(k,m) * B(k,n).
// TRANS_A=true : A global is [K x M] row-major (direct row copy into As).
// TRANS_A=false: A global is [M x K] row-major (transpose at SMEM fill).
template <bool TRANS_A>
__device__ __forceinline__ void gemm_core(
    const float* __restrict__ A, int lda,
    const float* __restrict__ B, int ldb,
    float* __restrict__ C, int ldc,
    int kbeg, int kend, int m0, int n0)
{
    __shared__ __align__(16) float As[BK * SL];
    __shared__ __align__(16) float Bs[BK * SL];

    const int tid = threadIdx.x;
    const int tx = tid & 15;        // n sub-tile: cols tx*8 .. tx*8+7
    const int ty = tid >> 4;        // m sub-tile: rows ty*8 .. ty*8+7
    // fill indices
    const int r_c4 = tid & 31, r_kr = tid >> 5;   // row-copy: 32 float4 per 128-wide row
    const int a_c4 = tid & 7,  a_mr = tid >> 3;   // NN transpose: 8 k-chunks, 32 m-rows/pass

    u64 acc[4][8] = {};   // [m-pair][n]

    for (int k0 = kbeg; k0 < kend; k0 += BK) {
        // ---- fill As ----
        if (TRANS_A) {
            #pragma unroll
            for (int p = 0; p < 4; p++) {
                int k = r_kr + p * 8;
                float4 v = *reinterpret_cast<const float4*>(
                    &A[(size_t)(k0 + k) * lda + m0 + r_c4 * 4]);
                *reinterpret_cast<float4*>(&As[k * SL + r_c4 * 4]) = v;
            }
        } else {
            #pragma unroll
            for (int p = 0; p < 4; p++) {
                int m = a_mr + p * 32;
                float4 v = *reinterpret_cast<const float4*>(
                    &A[(size_t)(m0 + m) * lda + k0 + a_c4 * 4]);
                As[(a_c4 * 4 + 0) * SL + m] = v.x;
                As[(a_c4 * 4 + 1) * SL + m] = v.y;
                As[(a_c4 * 4 + 2) * SL + m] = v.z;
                As[(a_c4 * 4 + 3) * SL + m] = v.w;
            }
        }
        // ---- fill Bs (B always [K x N] row-major) ----
        #pragma unroll
        for (int p = 0; p < 4; p++) {
            int k = r_kr + p * 8;
            float4 v = *reinterpret_cast<const float4*>(
                &B[(size_t)(k0 + k) * ldb + n0 + r_c4 * 4]);
            *reinterpret_cast<float4*>(&Bs[k * SL + r_c4 * 4]) = v;
        }
        __syncthreads();

        // ---- compute ----
        #pragma unroll
        for (int kk = 0; kk < BK; kk++) {
            // a: 8 consecutive floats = 4 natural m-pairs (no dup needed)
            ulonglong2 av0 = *reinterpret_cast<const ulonglong2*>(&As[kk * SL + ty * 8]);
            ulonglong2 av1 = *reinterpret_cast<const ulonglong2*>(&As[kk * SL + ty * 8 + 4]);
            u64 a[4] = {av0.x, av0.y, av1.x, av1.y};
            // b: 8 floats, duplicated into u64 in registers (MOVs hide in rt=2 gaps)
            float4 bv0 = *reinterpret_cast<const float4*>(&Bs[kk * SL + tx * 8]);
            float4 bv1 = *reinterpret_cast<const float4*>(&Bs[kk * SL + tx * 8 + 4]);
            u64 b[8];
            b[0] = dup2(bv0.x); b[1] = dup2(bv0.y); b[2] = dup2(bv0.z); b[3] = dup2(bv0.w);
            b[4] = dup2(bv1.x); b[5] = dup2(bv1.y); b[6] = dup2(bv1.z); b[7] = dup2(bv1.w);
            #pragma unroll
            for (int i = 0; i < 4; i++)
                #pragma unroll
                for (int j = 0; j < 8; j++)
                    acc[i][j] = fma2(a[i], b[j], acc[i][j]);
        }
        __syncthreads();
    }

    // ---- epilogue: acc[i][j] holds rows (2i, 2i+1) of col j ----
    #pragma unroll
    for (int i = 0; i < 4; i++) {
        int r0 = m0 + ty * 8 + 2 * i;
        float4 lo0, lo1, hi0, hi1;
        lo0.x = lo_f(acc[i][0]); lo0.y = lo_f(acc[i][1]); lo0.z = lo_f(acc[i][2]); lo0.w = lo_f(acc[i][3]);
        lo1.x = lo_f(acc[i][4]); lo1.y = lo_f(acc[i][5]); lo1.z = lo_f(acc[i][6]); lo1.w = lo_f(acc[i][7]);
        hi0.x = hi_f(acc[i][0]); hi0.y = hi_f(acc[i][1]); hi0.z = hi_f(acc[i][2]); hi0.w = hi_f(acc[i][3]);
        hi1.x = hi_f(acc[i][4]); hi1.y = hi_f(acc[i][5]); hi1.z = hi_f(acc[i][6]); hi1.w = hi_f(acc[i][7]);
        float* c0 = &C[(size_t)r0 * ldc + n0 + tx * 8];
        float* c1 = &C[(size_t)(r0 + 1) * ldc + n0 + tx * 8];
        *reinterpret_cast<float4*>(c0)     = lo0;
        *reinterpret_cast<float4*>(c0 + 4) = lo1;
        *reinterpret_cast<float4*>(c1)     = hi0;
        *reinterpret_cast<float4*>(c1 + 4) = hi1;
    }
}

// Stage A: G[b,q] = X^T X  (TN, K=2048 split 8) — grid (4, 8, 8) = 256 blocks
__global__ void __launch_bounds__(256, 2) k_gram(const float* __restrict__ hidden)
{
    const int pair = blockIdx.y;                  // b*4 + q
    const int b = pair >> 2, q = pair & 3;
    const float* X = hidden + (size_t)b * 2048 * 1024 + q * 256;
    float* C = g_Gp + ((size_t)blockIdx.z * 8 + pair) * 65536;
    const int m0 = (blockIdx.x >> 1) * BM, n0 = (blockIdx.x & 1) * BN;
    const int kbeg = blockIdx.z * 256;
    gemm_core<true>(X, 1024, X, 1024, C, 256, kbeg, kbeg + 256, m0, n0);
}

__global__ void __launch_bounds__(256) k_gred()
{
    const int i = blockIdx.x * 256 + threadIdx.x;     // 131072 float4
    const float4* P = reinterpret_cast<const float4*>(g_Gp);
    float4 s = P[i];
    #pragma unroll
    for (int z = 1; z < 8; z++) {
        float4 t = P[i + (size_t)z * 131072];
        s.x += t.x; s.y += t.y; s.z += t.z; s.w += t.w;
    }
    reinterpret_cast<float4*>(g_G)[i] = s;
}

// Stage B1: T[b,a][q*256+f, g] = G[b,q] @ C_{a,q} = G^T @ C (G symmetric -> TN direct)
// K=256 split 2 — grid (4, 32, 2) = 256 blocks
__global__ void __launch_bounds__(256, 2) k_gc(const float* __restrict__ comb)
{
    const int combo = blockIdx.y;                 // ((b*4+a)*4 + q)
    const int q = combo & 3, a = (combo >> 2) & 3, b = combo >> 4;
    const float* A = g_G + (size_t)(b * 4 + q) * 65536;
    const float* B = comb + ((size_t)a * 1024 + q * 256) * 256;
    float* C = g_Tp + (size_t)blockIdx.z * (8 * 1024 * 256)
                    + ((size_t)(b * 4 + a) * 1024 + q * 256) * 256;
    const int m0 = (blockIdx.x >> 1) * BM, n0 = (blockIdx.x & 1) * BN;
    const int kbeg = blockIdx.z * 128;
    gemm_core<true>(A, 256, B, 256, C, 256, kbeg, kbeg + 128, m0, n0);
}

__global__ void __launch_bounds__(256) k_tred()
{
    const int i = blockIdx.x * 256 + threadIdx.x;     // 524288 float4
    const float4* P = reinterpret_cast<const float4*>(g_Tp);
    float4 s = P[i];
    float4 t = P[i + 524288];
    s.x += t.x; s.y += t.y; s.z += t.z; s.w += t.w;
    reinterpret_cast<float4*>(g_T)[i] = s;
}

// Stage B2: M[b,a] = queries[a] (256x1024) @ T[b,a] (1024x256)  (NN, K split 8)
// grid (4, 8, 8) = 256 blocks
__global__ void __launch_bounds__(256, 2) k_fold(const float* __restrict__ queries)
{
    const int combo = blockIdx.y;                 // b*4 + a
    const int a = combo & 3;
    const float* A = queries + (size_t)a * 256 * 1024;
    const float* B = g_T + (size_t)combo * 1024 * 256;
    float* C = g_Mp + ((size_t)blockIdx.z * 8 + combo) * 65536;
    const int m0 = (blockIdx.x >> 1) * BM, n0 = (blockIdx.x & 1) * BN;
    const int kbeg = blockIdx.z * 128;
    gemm_core<false>(A, 1024, B, 256, C, 256, kbeg, kbeg + 128, m0, n0);
}

__global__ void __launch_bounds__(256) k_mred()
{
    const int i = blockIdx.x * 256 + threadIdx.x;     // 131072 float4
    const float4* P = reinterpret_cast<const float4*>(g_Mp);
    float4 s = P[i];
    #pragma unroll
    for (int z = 1; z < 8; z++) {
        float4 t = P[i + (size_t)z * 131072];
        s.x += t.x; s.y += t.y; s.z += t.z; s.w += t.w;
    }
    reinterpret_cast<float4*>(g_M)[i] = s;
}

// Stage C: out[b,:,a*256:(a+1)*256] = hidden[b,:,a*256:(a+1)*256] @ M[b,a]
// (NN, K=256) — grid (32, 8) = 256 blocks
__global__ void __launch_bounds__(256, 2) k_out(const float* __restrict__ hidden,
                                                float* __restrict__ out)
{
    const int combo = blockIdx.y;                 // b*4 + a
    const int b = combo >> 2, a = combo & 3;
    const float* A = hidden + (size_t)b * 2048 * 1024 + a * 256;
    const float* B = g_M + (size_t)combo * 65536;
    float* C = out + (size_t)b * 2048 * 1024 + a * 256;
    const int m0 = (blockIdx.x >> 1) * BM, n0 = (blockIdx.x & 1) * BN;
    gemm_core<false>(A, 1024, B, 256, C, 1024, 0, 256, m0, n0);
}

extern "C" void kernel_launch(void* const* d_in, const int* in_sizes, int n_in,
                              void* d_out, int out_size)
{
    const float* hidden  = (const float*)d_in[0];   // [2, 2048, 1024]
    const float* queries = (const float*)d_in[1];   // [4, 256, 1024]
    const float* comb    = (const float*)d_in[2];   // [4, 1024, 256]
    float* out = (float*)d_out;                     // [2, 2048, 1024]

    dim3 blk(256);
    k_gram<<<dim3(4, 8, 8), blk>>>(hidden);
    k_gred<<<512, 256>>>();
    k_gc  <<<dim3(4, 32, 2), blk>>>(comb);
    k_tred<<<2048, 256>>>();
    k_fold<<<dim3(4, 8, 8), blk>>>(queries);
    k_mred<<<512, 256>>>();
    k_out <<<dim3(32, 8), blk>>>(hidden, out);
}

// round 6
// speedup vs baseline: 2.6674x; 1.0073x over previous
#include <cuda_runtime.h>

typedef unsigned long long u64;

// Scratch (device globals; no allocations allowed).
__device__ __align__(16) float g_Gp[8 * 8 * 65536];     // gram partials (K-split 8)
__device__ __align__(16) float g_G [8 * 65536];         // G[b*4+q] 256x256 (symmetric)
__device__ __align__(16) float g_Tp[2 * 8 * 1024 * 256];// gc partials (K-split 2)
__device__ __align__(16) float g_T [8 * 1024 * 256];    // T[b*4+a] 1024x256
__device__ __align__(16) float g_Mp[8 * 8 * 65536];     // fold partials (K-split 8)
__device__ __align__(16) float g_M [8 * 65536];         // M[b*4+a] 256x256

__device__ __forceinline__ u64 fma2(u64 a, u64 b, u64 c) {
    u64 d;
    asm("fma.rn.f32x2 %0, %1, %2, %3;" : "=l"(d) : "l"(a), "l"(b), "l"(c));
    return d;
}
__device__ __forceinline__ u64 dup2(float x) {
    u64 d;
    asm("mov.b64 %0, {%1, %1};" : "=l"(d) : "f"(x));
    return d;
}
__device__ __forceinline__ float lo_f(u64 v) { return __uint_as_float((unsigned)v); }
__device__ __forceinline__ float hi_f(u64 v) { return __uint_as_float((unsigned)(v >> 32)); }

// 128x128 tile, BK=32, 256 threads, 8m x 8n micro-tile.
// As[k][m], Bs[k][n] both k-major, un-duplicated (minimal LDS bytes).
constexpr int BM = 128, BN = 128, BK = 32;
constexpr int SL = 132;   // row stride in floats (132*4=528 = 16*33, 16B-aligned rows)

// C[m,n] += sum_k A(k,m) * B(k,n).
// TRANS_A=true : A global is [K x M] row-major (direct row copy into As).
// TRANS_A=false: A global is [M x K] row-major (transpose at SMEM fill).
template <bool TRANS_A>
__device__ __forceinline__ void gemm_core(
    const float* __restrict__ A, int lda,
    const float* __restrict__ B, int ldb,
    float* __restrict__ C, int ldc,
    int kbeg, int kend, int m0, int n0)
{
    __shared__ __align__(16) float As[BK * SL];
    __shared__ __align__(16) float Bs[BK * SL];

    const int tid = threadIdx.x;
    const int tx = tid & 15;        // n sub-tile: cols tx*8 .. tx*8+7
    const int ty = tid >> 4;        // m sub-tile: rows ty*8 .. ty*8+7
    // fill indices
    const int r_c4 = tid & 31, r_kr = tid >> 5;   // row-copy: 32 float4 per 128-wide row
    const int a_c4 = tid & 7,  a_mr = tid >> 3;   // NN transpose: 8 k-chunks, 32 m-rows/pass

    u64 acc[4][8] = {};   // [m-pair][n]

    for (int k0 = kbeg; k0 < kend; k0 += BK) {
        // ---- fill As ----
        if (TRANS_A) {
            #pragma unroll
            for (int p = 0; p < 4; p++) {
                int k = r_kr + p * 8;
                float4 v = *reinterpret_cast<const float4*>(
                    &A[(size_t)(k0 + k) * lda + m0 + r_c4 * 4]);
                *reinterpret_cast<float4*>(&As[k * SL + r_c4 * 4]) = v;
            }
        } else {
            #pragma unroll
            for (int p = 0; p < 4; p++) {
                int m = a_mr + p * 32;
                float4 v = *reinterpret_cast<const float4*>(
                    &A[(size_t)(m0 + m) * lda + k0 + a_c4 * 4]);
                As[(a_c4 * 4 + 0) * SL + m] = v.x;
                As[(a_c4 * 4 + 1) * SL + m] = v.y;
                As[(a_c4 * 4 + 2) * SL + m] = v.z;
                As[(a_c4 * 4 + 3) * SL + m] = v.w;
            }
        }
        // ---- fill Bs (B always [K x N] row-major) ----
        #pragma unroll
        for (int p = 0; p < 4; p++) {
            int k = r_kr + p * 8;
            float4 v = *reinterpret_cast<const float4*>(
                &B[(size_t)(k0 + k) * ldb + n0 + r_c4 * 4]);
            *reinterpret_cast<float4*>(&Bs[k * SL + r_c4 * 4]) = v;
        }
        __syncthreads();

        // ---- compute ----
        #pragma unroll
        for (int kk = 0; kk < BK; kk++) {
            // a: 8 consecutive floats = 4 natural m-pairs (no dup needed)
            ulonglong2 av0 = *reinterpret_cast<const ulonglong2*>(&As[kk * SL + ty * 8]);
            ulonglong2 av1 = *reinterpret_cast<const ulonglong2*>(&As[kk * SL + ty * 8 + 4]);
            u64 a[4] = {av0.x, av0.y, av1.x, av1.y};
            // b: 8 floats, duplicated into u64 in registers (MOVs hide in rt=2 gaps)
            float4 bv0 = *reinterpret_cast<const float4*>(&Bs[kk * SL + tx * 8]);
            float4 bv1 = *reinterpret_cast<const float4*>(&Bs[kk * SL + tx * 8 + 4]);
            u64 b[8];
            b[0] = dup2(bv0.x); b[1] = dup2(bv0.y); b[2] = dup2(bv0.z); b[3] = dup2(bv0.w);
            b[4] = dup2(bv1.x); b[5] = dup2(bv1.y); b[6] = dup2(bv1.z); b[7] = dup2(bv1.w);
            #pragma unroll
            for (int i = 0; i < 4; i++)
                #pragma unroll
                for (int j = 0; j < 8; j++)
                    acc[i][j] = fma2(a[i], b[j], acc[i][j]);
        }
        __syncthreads();
    }

    // ---- epilogue: acc[i][j] holds rows (2i, 2i+1) of col j ----
    #pragma unroll
    for (int i = 0; i < 4; i++) {
        int r0 = m0 + ty * 8 + 2 * i;
        float4 lo0, lo1, hi0, hi1;
        lo0.x = lo_f(acc[i][0]); lo0.y = lo_f(acc[i][1]); lo0.z = lo_f(acc[i][2]); lo0.w = lo_f(acc[i][3]);
        lo1.x = lo_f(acc[i][4]); lo1.y = lo_f(acc[i][5]); lo1.z = lo_f(acc[i][6]); lo1.w = lo_f(acc[i][7]);
        hi0.x = hi_f(acc[i][0]); hi0.y = hi_f(acc[i][1]); hi0.z = hi_f(acc[i][2]); hi0.w = hi_f(acc[i][3]);
        hi1.x = hi_f(acc[i][4]); hi1.y = hi_f(acc[i][5]); hi1.z = hi_f(acc[i][6]); hi1.w = hi_f(acc[i][7]);
        float* c0 = &C[(size_t)r0 * ldc + n0 + tx * 8];
        float* c1 = &C[(size_t)(r0 + 1) * ldc + n0 + tx * 8];
        *reinterpret_cast<float4*>(c0)     = lo0;
        *reinterpret_cast<float4*>(c0 + 4) = lo1;
        *reinterpret_cast<float4*>(c1)     = hi0;
        *reinterpret_cast<float4*>(c1 + 4) = hi1;
    }
}

// Stage A: G[b,q] = X^T X  (TN, K=2048 split 8) — grid (4, 8, 8) = 256 blocks
__global__ void __launch_bounds__(256, 2) k_gram(const float* __restrict__ hidden)
{
    const int pair = blockIdx.y;                  // b*4 + q
    const int b = pair >> 2, q = pair & 3;
    const float* X = hidden + (size_t)b * 2048 * 1024 + q * 256;
    float* C = g_Gp + ((size_t)blockIdx.z * 8 + pair) * 65536;
    const int m0 = (blockIdx.x >> 1) * BM, n0 = (blockIdx.x & 1) * BN;
    const int kbeg = blockIdx.z * 256;
    gemm_core<true>(X, 1024, X, 1024, C, 256, kbeg, kbeg + 256, m0, n0);
}

__global__ void __launch_bounds__(256) k_gred()
{
    const int i = blockIdx.x * 256 + threadIdx.x;     // 131072 float4
    const float4* P = reinterpret_cast<const float4*>(g_Gp);
    float4 s = P[i];
    #pragma unroll
    for (int z = 1; z < 8; z++) {
        float4 t = P[i + (size_t)z * 131072];
        s.x += t.x; s.y += t.y; s.z += t.z; s.w += t.w;
    }
    reinterpret_cast<float4*>(g_G)[i] = s;
}

// Stage B1: T[b,a][q*256+f, g] = G[b,q] @ C_{a,q} = G^T @ C (G symmetric -> TN direct)
// K=256 split 2 — grid (4, 32, 2) = 256 blocks
__global__ void __launch_bounds__(256, 2) k_gc(const float* __restrict__ comb)
{
    const int combo = blockIdx.y;                 // ((b*4+a)*4 + q)
    const int q = combo & 3, a = (combo >> 2) & 3, b = combo >> 4;
    const float* A = g_G + (size_t)(b * 4 + q) * 65536;
    const float* B = comb + ((size_t)a * 1024 + q * 256) * 256;
    float* C = g_Tp + (size_t)blockIdx.z * (8 * 1024 * 256)
                    + ((size_t)(b * 4 + a) * 1024 + q * 256) * 256;
    const int m0 = (blockIdx.x >> 1) * BM, n0 = (blockIdx.x & 1) * BN;
    const int kbeg = blockIdx.z * 128;
    gemm_core<true>(A, 256, B, 256, C, 256, kbeg, kbeg + 128, m0, n0);
}

__global__ void __launch_bounds__(256) k_tred()
{
    const int i = blockIdx.x * 256 + threadIdx.x;     // 524288 float4
    const float4* P = reinterpret_cast<const float4*>(g_Tp);
    float4 s = P[i];
    float4 t = P[i + 524288];
    s.x += t.x; s.y += t.y; s.z += t.z; s.w += t.w;
    reinterpret_cast<float4*>(g_T)[i] = s;
}

// Stage B2: M[b,a] = queries[a] (256x1024) @ T[b,a] (1024x256)  (NN, K split 8)
// grid (4, 8, 8) = 256 blocks
__global__ void __launch_bounds__(256, 2) k_fold(const float* __restrict__ queries)
{
    const int combo = blockIdx.y;                 // b*4 + a
    const int a = combo & 3;
    const float* A = queries + (size_t)a * 256 * 1024;
    const float* B = g_T + (size_t)combo * 1024 * 256;
    float* C = g_Mp + ((size_t)blockIdx.z * 8 + combo) * 65536;
    const int m0 = (blockIdx.x >> 1) * BM, n0 = (blockIdx.x & 1) * BN;
    const int kbeg = blockIdx.z * 128;
    gemm_core<false>(A, 1024, B, 256, C, 256, kbeg, kbeg + 128, m0, n0);
}

__global__ void __launch_bounds__(256) k_mred()
{
    const int i = blockIdx.x * 256 + threadIdx.x;     // 131072 float4
    const float4* P = reinterpret_cast<const float4*>(g_Mp);
    float4 s = P[i];
    #pragma unroll
    for (int z = 1; z < 8; z++) {
        float4 t = P[i + (size_t)z * 131072];
        s.x += t.x; s.y += t.y; s.z += t.z; s.w += t.w;
    }
    reinterpret_cast<float4*>(g_M)[i] = s;
}

// Stage C: out[b,:,a*256:(a+1)*256] = hidden[b,:,a*256:(a+1)*256] @ M[b,a]
// (NN, K=256) — grid (32, 8) = 256 blocks
__global__ void __launch_bounds__(256, 2) k_out(const float* __restrict__ hidden,
                                                float* __restrict__ out)
{
    const int combo = blockIdx.y;                 // b*4 + a
    const int b = combo >> 2, a = combo & 3;
    const float* A = hidden + (size_t)b * 2048 * 1024 + a * 256;
    const float* B = g_M + (size_t)combo * 65536;
    float* C = out + (size_t)b * 2048 * 1024 + a * 256;
    const int m0 = (blockIdx.x >> 1) * BM, n0 = (blockIdx.x & 1) * BN;
    gemm_core<false>(A, 1024, B, 256, C, 1024, 0, 256, m0, n0);
}

extern "C" void kernel_launch(void* const* d_in, const int* in_sizes, int n_in,
                              void* d_out, int out_size)
{
    const float* hidden  = (const float*)d_in[0];   // [2, 2048, 1024]
    const float* queries = (const float*)d_in[1];   // [4, 256, 1024]
    const float* comb    = (const float*)d_in[2];   // [4, 1024, 256]
    float* out = (float*)d_out;                     // [2, 2048, 1024]

    dim3 blk(256);
    k_gram<<<dim3(4, 8, 8), blk>>>(hidden);
    k_gred<<<512, 256>>>();
    k_gc  <<<dim3(4, 32, 2), blk>>>(comb);
    k_tred<<<2048, 256>>>();
    k_fold<<<dim3(4, 8, 8), blk>>>(queries);
    k_mred<<<512, 256>>>();
    k_out <<<dim3(32, 8), blk>>>(hidden, out);
}

// round 8
// speedup vs baseline: 3.5919x; 1.3466x over previous
#include <cuda_runtime.h>
#include <cuda_bf16.h>
#include <cstdint>

typedef unsigned int u32;
typedef unsigned short u16;

// ---------------------------------------------------------------------------
// Device-global scratch (no allocations allowed). All bf16 stored as ushort.
// ---------------------------------------------------------------------------
__device__ __align__(16) u16 g_XTh[8u*256*2048], g_XTl[8u*256*2048];  // X^T per (b,q): [f=256][t=2048]
__device__ __align__(16) u16 g_Xnh[2u*2048*1024], g_Xnl[2u*2048*1024];// hidden split: [b][t][e]
__device__ __align__(16) u16 g_CTh[16u*65536],   g_CTl[16u*65536];    // C^T per (a,q): [g=256][f=256]
__device__ __align__(16) u16 g_qh [4u*262144],   g_ql [4u*262144];    // queries split: [a][e=256][k=1024]
__device__ __align__(16) float g_Gp[8u*8*65536];                      // gram fp32 partials (z8)
__device__ __align__(16) u16 g_Gh[8u*65536], g_Gl[8u*65536];          // G per (b,q): [256][256] (symmetric)
__device__ __align__(16) float g_Tf[8u*262144];                       // T^T fp32: [ba][g=256][k=1024]
__device__ __align__(16) u16 g_TTh[8u*262144], g_TTl[8u*262144];      // T^T split
__device__ __align__(16) float g_Mp[4u*8*65536];                      // fold fp32 partials (z4)
__device__ __align__(16) u16 g_Mth[8u*65536], g_Mtl[8u*65536];        // M^T per (b,a): [g=256][e=256]

// ---------------------------------------------------------------------------
__device__ __forceinline__ void mma_bf16(float* c, const u32* a, const u32* b) {
    asm("mma.sync.aligned.m16n8k16.row.col.f32.bf16.bf16.f32 "
        "{%0,%1,%2,%3}, {%4,%5,%6,%7}, {%8,%9}, {%0,%1,%2,%3};"
        : "+f"(c[0]), "+f"(c[1]), "+f"(c[2]), "+f"(c[3])
        : "r"(a[0]), "r"(a[1]), "r"(a[2]), "r"(a[3]), "r"(b[0]), "r"(b[1]));
}

__device__ __forceinline__ void split2(float v, u16& h, u16& l) {
    __nv_bfloat16 bh = __float2bfloat16(v);
    __nv_bfloat16 bl = __float2bfloat16(v - __bfloat162float(bh));
    h = *reinterpret_cast<u16*>(&bh);
    l = *reinterpret_cast<u16*>(&bl);
}

// SMEM tile: 128 rows x 32 bf16, row stride 40 ushorts (80B: 16B-aligned,
// conflict-free for the m16n8k16 fragment LDS pattern).
constexpr int SK = 40;

__device__ __forceinline__ void fill_tile(u16* __restrict__ s, const u16* __restrict__ g,
                                          size_t ld, int k0)
{
    #pragma unroll
    for (int u = threadIdx.x; u < 512; u += 256) {
        int row = u >> 2, c = u & 3;
        uint4 v = *reinterpret_cast<const uint4*>(g + (size_t)row * ld + k0 + c * 8);
        *reinterpret_cast<uint4*>(s + row * SK + c * 8) = v;
    }
}

// ---------------------------------------------------------------------------
// Core: C[128,128](fp32, row-major ldc) = sum_k (Ah+Al)[128,k]*(Bh+Bl)[128,k]^T
// A,B K-major bf16-split gmem, pre-offset to tile origin. hh+hl+lh products.
// 256 threads = 8 warps (2m x 4n), warp tile 64x32.
// ---------------------------------------------------------------------------
__device__ void gemm_ss(const u16* __restrict__ Ah, const u16* __restrict__ Al, size_t lda,
                        const u16* __restrict__ Bh, const u16* __restrict__ Bl, size_t ldb,
                        int kbeg, int kend, float* __restrict__ C, size_t ldc)
{
    __shared__ __align__(16) u16 sAh[128 * SK], sAl[128 * SK];
    __shared__ __align__(16) u16 sBh[128 * SK], sBl[128 * SK];

    const int tid = threadIdx.x, w = tid >> 5, lane = tid & 31;
    const int wm = (w >> 2) * 64, wn = (w & 3) * 32;
    const int ty = lane >> 2, tk = lane & 3;

    float acc[4][4][4] = {};   // [mt][nt][frag]

    for (int k0 = kbeg; k0 < kend; k0 += 32) {
        fill_tile(sAh, Ah, lda, k0);
        fill_tile(sAl, Al, lda, k0);
        fill_tile(sBh, Bh, ldb, k0);
        fill_tile(sBl, Bl, ldb, k0);
        __syncthreads();

        #pragma unroll
        for (int ks = 0; ks < 2; ks++) {
            const int kb = ks * 16 + tk * 2;
            u32 bh[4][2], bl[4][2];
            #pragma unroll
            for (int nt = 0; nt < 4; nt++) {
                int n = wn + nt * 8 + ty;
                bh[nt][0] = *reinterpret_cast<const u32*>(&sBh[n * SK + kb]);
                bh[nt][1] = *reinterpret_cast<const u32*>(&sBh[n * SK + kb + 8]);
                bl[nt][0] = *reinterpret_cast<const u32*>(&sBl[n * SK + kb]);
                bl[nt][1] = *reinterpret_cast<const u32*>(&sBl[n * SK + kb + 8]);
            }
            #pragma unroll
            for (int mt = 0; mt < 4; mt++) {
                int m = wm + mt * 16 + ty;
                u32 ah[4], al[4];
                ah[0] = *reinterpret_cast<const u32*>(&sAh[m * SK + kb]);
                ah[1] = *reinterpret_cast<const u32*>(&sAh[(m + 8) * SK + kb]);
                ah[2] = *reinterpret_cast<const u32*>(&sAh[m * SK + kb + 8]);
                ah[3] = *reinterpret_cast<const u32*>(&sAh[(m + 8) * SK + kb + 8]);
                al[0] = *reinterpret_cast<const u32*>(&sAl[m * SK + kb]);
                al[1] = *reinterpret_cast<const u32*>(&sAl[(m + 8) * SK + kb]);
                al[2] = *reinterpret_cast<const u32*>(&sAl[m * SK + kb + 8]);
                al[3] = *reinterpret_cast<const u32*>(&sAl[(m + 8) * SK + kb + 8]);
                #pragma unroll
                for (int nt = 0; nt < 4; nt++) {
                    mma_bf16(acc[mt][nt], ah, bh[nt]);
                    mma_bf16(acc[mt][nt], ah, bl[nt]);
                    mma_bf16(acc[mt][nt], al, bh[nt]);
                }
            }
        }
        __syncthreads();
    }

    // epilogue (fp32)
    #pragma unroll
    for (int mt = 0; mt < 4; mt++) {
        int m = wm + mt * 16 + ty;
        #pragma unroll
        for (int nt = 0; nt < 4; nt++) {
            int n = wn + nt * 8 + tk * 2;
            *reinterpret_cast<float2*>(&C[(size_t)m * ldc + n]) =
                make_float2(acc[mt][nt][0], acc[mt][nt][1]);
            *reinterpret_cast<float2*>(&C[(size_t)(m + 8) * ldc + n]) =
                make_float2(acc[mt][nt][2], acc[mt][nt][3]);
        }
    }
}

// ---------------------------------------------------------------------------
// Prep kernels (fp32 -> bf16 hi/lo, with transposes)
// ---------------------------------------------------------------------------
__global__ void __launch_bounds__(256) p_hid(const float* __restrict__ hidden)
{
    __shared__ float tile[64][65];
    const int tid = threadIdx.x;
    const int e0 = blockIdx.x * 64, t0 = blockIdx.y * 64, b = blockIdx.z;
    const size_t base = (size_t)b * 2048 * 1024;
    for (int i = tid; i < 4096; i += 256) {
        int r = i >> 6, c = i & 63;
        float v = hidden[base + (size_t)(t0 + r) * 1024 + e0 + c];
        tile[r][c] = v;
        u16 h, l; split2(v, h, l);
        size_t o = base + (size_t)(t0 + r) * 1024 + e0 + c;
        g_Xnh[o] = h; g_Xnl[o] = l;
    }
    __syncthreads();
    const int pair = b * 4 + (e0 >> 8), f0 = e0 & 255;
    for (int i = tid; i < 4096; i += 256) {
        int fl = i >> 6, tl = i & 63;
        u16 h, l; split2(tile[tl][fl], h, l);
        size_t o = (size_t)pair * 524288 + (size_t)(f0 + fl) * 2048 + t0 + tl;
        g_XTh[o] = h; g_XTl[o] = l;
    }
}

__global__ void __launch_bounds__(256) p_comb(const float* __restrict__ comb)
{
    __shared__ float tile[64][65];
    const int tid = threadIdx.x;
    const int g0 = blockIdx.x * 64, k0 = blockIdx.y * 64, a = blockIdx.z;
    for (int i = tid; i < 4096; i += 256) {
        int r = i >> 6, c = i & 63;
        tile[r][c] = comb[(size_t)a * 262144 + (size_t)(k0 + r) * 256 + g0 + c];
    }
    __syncthreads();
    const int q = k0 >> 8, f0 = k0 & 255;
    for (int i = tid; i < 4096; i += 256) {
        int gl = i >> 6, fl = i & 63;
        u16 h, l; split2(tile[fl][gl], h, l);
        size_t o = (size_t)(a * 4 + q) * 65536 + (size_t)(g0 + gl) * 256 + f0 + fl;
        g_CTh[o] = h; g_CTl[o] = l;
    }
}

__global__ void __launch_bounds__(256) p_q(const float* __restrict__ queries)
{
    const int i = blockIdx.x * 256 + threadIdx.x;      // 262144 float4
    float4 v = reinterpret_cast<const float4*>(queries)[i];
    ushort4 h, l;
    split2(v.x, h.x, l.x); split2(v.y, h.y, l.y);
    split2(v.z, h.z, l.z); split2(v.w, h.w, l.w);
    reinterpret_cast<ushort4*>(g_qh)[i] = h;
    reinterpret_cast<ushort4*>(g_ql)[i] = l;
}

// ---------------------------------------------------------------------------
// GEMM stages
// ---------------------------------------------------------------------------
// Gram: D[f,f'] = sum_t XT[f,t] XT[f',t]  — grid (4, 8 pairs, 8 z)
__global__ void __launch_bounds__(256) k_gram()
{
    const int pair = blockIdx.y, z = blockIdx.z;
    const int m0 = (blockIdx.x >> 1) * 128, n0 = (blockIdx.x & 1) * 128;
    const u16* base_h = g_XTh + (size_t)pair * 524288;
    const u16* base_l = g_XTl + (size_t)pair * 524288;
    float* C = g_Gp + (size_t)(z * 8 + pair) * 65536 + (size_t)m0 * 256 + n0;
    gemm_ss(base_h + (size_t)m0 * 2048, base_l + (size_t)m0 * 2048, 2048,
            base_h + (size_t)n0 * 2048, base_l + (size_t)n0 * 2048, 2048,
            z * 256, z * 256 + 256, C, 256);
}

__global__ void __launch_bounds__(256) k_gred()
{
    const int i = blockIdx.x * 256 + threadIdx.x;      // 131072 float4
    const float4* P = reinterpret_cast<const float4*>(g_Gp);
    float4 s = P[i];
    #pragma unroll
    for (int z = 1; z < 8; z++) {
        float4 t = P[i + (size_t)z * 131072];
        s.x += t.x; s.y += t.y; s.z += t.z; s.w += t.w;
    }
    ushort4 h, l;
    split2(s.x, h.x, l.x); split2(s.y, h.y, l.y);
    split2(s.z, h.z, l.z); split2(s.w, h.w, l.w);
    reinterpret_cast<ushort4*>(g_Gh)[i] = h;
    reinterpret_cast<ushort4*>(g_Gl)[i] = l;
}

// B1: Tf[ba][g, q*256+f] = sum_{f'} CT[a,q][g,f'] G[b,q][f,f'] — grid (4, 32)
__global__ void __launch_bounds__(256) k_b1()
{
    const int combo = blockIdx.y, q = combo & 3, ba = combo >> 2;
    const int a = ba & 3, b = ba >> 2;
    const int m0 = (blockIdx.x >> 1) * 128, n0 = (blockIdx.x & 1) * 128;
    const u16* Ah = g_CTh + (size_t)(a * 4 + q) * 65536 + (size_t)m0 * 256;
    const u16* Al = g_CTl + (size_t)(a * 4 + q) * 65536 + (size_t)m0 * 256;
    const u16* Bh = g_Gh + (size_t)(b * 4 + q) * 65536 + (size_t)n0 * 256;
    const u16* Bl = g_Gl + (size_t)(b * 4 + q) * 65536 + (size_t)n0 * 256;
    float* C = g_Tf + (size_t)ba * 262144 + (size_t)m0 * 1024 + q * 256 + n0;
    gemm_ss(Ah, Al, 256, Bh, Bl, 256, 0, 256, C, 1024);
}

__global__ void __launch_bounds__(256) k_tred()
{
    const int i = blockIdx.x * 256 + threadIdx.x;      // 524288 float4
    float4 s = reinterpret_cast<const float4*>(g_Tf)[i];
    ushort4 h, l;
    split2(s.x, h.x, l.x); split2(s.y, h.y, l.y);
    split2(s.z, h.z, l.z); split2(s.w, h.w, l.w);
    reinterpret_cast<ushort4*>(g_TTh)[i] = h;
    reinterpret_cast<ushort4*>(g_TTl)[i] = l;
}

// B2: Mt[g,e] = sum_k TT[ba][g,k] q[a][e,k] — grid (4, 8 ba, 4 z)
__global__ void __launch_bounds__(256) k_b2()
{
    const int ba = blockIdx.y, z = blockIdx.z, a = ba & 3;
    const int m0 = (blockIdx.x >> 1) * 128, n0 = (blockIdx.x & 1) * 128;
    const u16* Ah = g_TTh + (size_t)ba * 262144 + (size_t)m0 * 1024;
    const u16* Al = g_TTl + (size_t)ba * 262144 + (size_t)m0 * 1024;
    const u16* Bh = g_qh + (size_t)a * 262144 + (size_t)n0 * 1024;
    const u16* Bl = g_ql + (size_t)a * 262144 + (size_t)n0 * 1024;
    float* C = g_Mp + (size_t)(z * 8 + ba) * 65536 + (size_t)m0 * 256 + n0;
    gemm_ss(Ah, Al, 1024, Bh, Bl, 1024, z * 256, z * 256 + 256, C, 256);
}

__global__ void __launch_bounds__(256) k_mred()
{
    const int i = blockIdx.x * 256 + threadIdx.x;      // 131072 float4
    const float4* P = reinterpret_cast<const float4*>(g_Mp);
    float4 s = P[i];
    #pragma unroll
    for (int z = 1; z < 4; z++) {
        float4 t = P[i + (size_t)z * 131072];
        s.x += t.x; s.y += t.y; s.z += t.z; s.w += t.w;
    }
    ushort4 h, l;
    split2(s.x, h.x, l.x); split2(s.y, h.y, l.y);
    split2(s.z, h.z, l.z); split2(s.w, h.w, l.w);
    reinterpret_cast<ushort4*>(g_Mth)[i] = h;
    reinterpret_cast<ushort4*>(g_Mtl)[i] = l;
}

// C: out[b,t,a*256+g] = sum_e Xn[b,t,a*256+e] Mt[ba][g,e] — grid (32, 8 ba)
__global__ void __launch_bounds__(256) k_c(float* __restrict__ out)
{
    const int ba = blockIdx.y, b = ba >> 2, a = ba & 3;
    const int m0 = (blockIdx.x >> 1) * 128, n0 = (blockIdx.x & 1) * 128;
    const u16* Ah = g_Xnh + (size_t)b * 2097152 + (size_t)m0 * 1024 + a * 256;
    const u16* Al = g_Xnl + (size_t)b * 2097152 + (size_t)m0 * 1024 + a * 256;
    const u16* Bh = g_Mth + (size_t)ba * 65536 + (size_t)n0 * 256;
    const u16* Bl = g_Mtl + (size_t)ba * 65536 + (size_t)n0 * 256;
    float* C = out + (size_t)b * 2097152 + (size_t)m0 * 1024 + a * 256 + n0;
    gemm_ss(Ah, Al, 1024, Bh, Bl, 256, 0, 256, C, 1024);
}

// ---------------------------------------------------------------------------
extern "C" void kernel_launch(void* const* d_in, const int* in_sizes, int n_in,
                              void* d_out, int out_size)
{
    const float* hidden  = (const float*)d_in[0];   // [2, 2048, 1024]
    const float* queries = (const float*)d_in[1];   // [4, 256, 1024]
    const float* comb    = (const float*)d_in[2];   // [4, 1024, 256]
    float* out = (float*)d_out;                     // [2, 2048, 1024]

    p_hid <<<dim3(16, 32, 2), 256>>>(hidden);
    p_comb<<<dim3(4, 16, 4), 256>>>(comb);
    p_q   <<<1024, 256>>>(queries);
    k_gram<<<dim3(4, 8, 8), 256>>>();
    k_gred<<<512, 256>>>();
    k_b1  <<<dim3(4, 32), 256>>>();
    k_tred<<<2048, 256>>>();
    k_b2  <<<dim3(4, 8, 4), 256>>>();
    k_mred<<<512, 256>>>();
    k_c   <<<dim3(32, 8), 256>>>(out);
}

// round 9
// speedup vs baseline: 4.2960x; 1.1960x over previous
#include <cuda_runtime.h>
#include <cuda_bf16.h>
#include <cstdint>

typedef unsigned int u32;
typedef unsigned short u16;

// ---------------------------------------------------------------------------
// Device-global scratch (no allocations allowed). All bf16 stored as ushort.
// ---------------------------------------------------------------------------
__device__ __align__(16) u16 g_XTh[8u*256*2048], g_XTl[8u*256*2048];  // X^T per (b,q): [f=256][t=2048]
__device__ __align__(16) u16 g_Xnh[2u*2048*1024], g_Xnl[2u*2048*1024];// hidden split: [b][t][e]
__device__ __align__(16) u16 g_CTh[16u*65536],   g_CTl[16u*65536];    // C^T per (a,q): [g=256][f=256]
__device__ __align__(16) u16 g_qh [4u*262144],   g_ql [4u*262144];    // queries split: [a][e=256][k=1024]
__device__ __align__(16) float g_Gp[8u*8*65536];                      // gram fp32 partials (z8)
__device__ __align__(16) u16 g_Gh[8u*65536], g_Gl[8u*65536];          // G per (b,q): [256][256] (symmetric)
__device__ __align__(16) float g_Tf[8u*262144];                       // T^T fp32: [ba][g=256][k=1024]
__device__ __align__(16) u16 g_TTh[8u*262144], g_TTl[8u*262144];      // T^T split
__device__ __align__(16) float g_Mp[4u*8*65536];                      // fold fp32 partials (z4)
__device__ __align__(16) u16 g_Mth[8u*65536], g_Mtl[8u*65536];        // M^T per (b,a): [g=256][e=256]

// ---------------------------------------------------------------------------
__device__ __forceinline__ void mma_bf16(float* c, const u32* a, const u32* b) {
    asm("mma.sync.aligned.m16n8k16.row.col.f32.bf16.bf16.f32 "
        "{%0,%1,%2,%3}, {%4,%5,%6,%7}, {%8,%9}, {%0,%1,%2,%3};"
        : "+f"(c[0]), "+f"(c[1]), "+f"(c[2]), "+f"(c[3])
        : "r"(a[0]), "r"(a[1]), "r"(a[2]), "r"(a[3]), "r"(b[0]), "r"(b[1]));
}
__device__ __forceinline__ void ldsm_x4(u32* r, u32 saddr) {
    asm volatile("ldmatrix.sync.aligned.m8n8.x4.shared.b16 {%0,%1,%2,%3}, [%4];"
                 : "=r"(r[0]), "=r"(r[1]), "=r"(r[2]), "=r"(r[3]) : "r"(saddr));
}
__device__ __forceinline__ void ldsm_x2(u32* r, u32 saddr) {
    asm volatile("ldmatrix.sync.aligned.m8n8.x2.shared.b16 {%0,%1}, [%2];"
                 : "=r"(r[0]), "=r"(r[1]) : "r"(saddr));
}
__device__ __forceinline__ void cpa16(u32 dst, const void* src) {
    asm volatile("cp.async.cg.shared.global [%0], [%1], 16;" :: "r"(dst), "l"(src));
}
__device__ __forceinline__ void cpa_commit() {
    asm volatile("cp.async.commit_group;" ::: "memory");
}

__device__ __forceinline__ void split2(float v, u16& h, u16& l) {
    __nv_bfloat16 bh = __float2bfloat16(v);
    __nv_bfloat16 bl = __float2bfloat16(v - __bfloat162float(bh));
    h = *reinterpret_cast<u16*>(&bh);
    l = *reinterpret_cast<u16*>(&bl);
}

// SMEM tile: 128 rows x 32 bf16, row stride 40 u16 (80B: 16B-aligned fills,
// conflict-free for ldmatrix row fetches: banks 0,20,8,28,16,4,24,12).
constexpr int SK = 40;
constexpr int TSZ = 128 * SK;                   // u16 per tile
constexpr int BUF = 4 * TSZ;                    // u16 per buffer (Ah,Al,Bh,Bl)
constexpr int SMEM_GEMM = 2 * BUF * 2;          // bytes = 81920

// ---------------------------------------------------------------------------
// cp.async fill of one 4-tile chunk (A/B hi+lo, 128x32 each)
// ---------------------------------------------------------------------------
__device__ __forceinline__ void issue_chunk(u16* buf,
    const u16* __restrict__ Ah, const u16* __restrict__ Al, size_t lda,
    const u16* __restrict__ Bh, const u16* __restrict__ Bl, size_t ldb, int k0)
{
    u16* sAh = buf;           u16* sAl = buf + TSZ;
    u16* sBh = buf + 2 * TSZ; u16* sBl = buf + 3 * TSZ;
    #pragma unroll
    for (int u = threadIdx.x; u < 512; u += 256) {
        int row = u >> 2, c = u & 3;
        int so = row * SK + c * 8;
        size_t goA = (size_t)row * lda + k0 + c * 8;
        size_t goB = (size_t)row * ldb + k0 + c * 8;
        cpa16((u32)__cvta_generic_to_shared(sAh + so), Ah + goA);
        cpa16((u32)__cvta_generic_to_shared(sAl + so), Al + goA);
        cpa16((u32)__cvta_generic_to_shared(sBh + so), Bh + goB);
        cpa16((u32)__cvta_generic_to_shared(sBl + so), Bl + goB);
    }
    cpa_commit();
}

// ---------------------------------------------------------------------------
// Core: C[128,128](fp32) = sum_k (Ah+Al)[128,k]*(Bh+Bl)[128,k]^T (hh+hl+lh)
// 256 threads = 8 warps (2m x 4n), warp tile 64x32. Double-buffered cp.async,
// ldmatrix fragment loads.
// ---------------------------------------------------------------------------
__device__ void gemm_ss(const u16* __restrict__ Ah, const u16* __restrict__ Al, size_t lda,
                        const u16* __restrict__ Bh, const u16* __restrict__ Bl, size_t ldb,
                        int kbeg, int kend, float* __restrict__ C, size_t ldc)
{
    extern __shared__ __align__(16) u16 dsmem[];
    u16* bufs[2] = { dsmem, dsmem + BUF };

    const int tid = threadIdx.x, w = tid >> 5, lane = tid & 31;
    const int wm = (w >> 2) * 64, wn = (w & 3) * 32;
    const int ty = lane >> 2, tk = lane & 3;

    float acc[4][4][4] = {};   // [mt][nt][frag]

    const int nchunk = (kend - kbeg) >> 5;
    issue_chunk(bufs[0], Ah, Al, lda, Bh, Bl, ldb, kbeg);

    for (int i = 0; i < nchunk; i++) {
        const bool has_next = (i + 1) < nchunk;
        if (has_next)
            issue_chunk(bufs[(i + 1) & 1], Ah, Al, lda, Bh, Bl, ldb, kbeg + (i + 1) * 32);
        if (has_next) asm volatile("cp.async.wait_group 1;" ::: "memory");
        else          asm volatile("cp.async.wait_group 0;" ::: "memory");
        __syncthreads();

        u16* buf = bufs[i & 1];
        const u32 bAh = (u32)__cvta_generic_to_shared(buf);
        const u32 bAl = bAh + TSZ * 2;
        const u32 bBh = bAh + 2 * TSZ * 2;
        const u32 bBl = bAh + 3 * TSZ * 2;

        #pragma unroll
        for (int ks = 0; ks < 2; ks++) {
            const int kb = ks * 16;
            u32 bh[4][2], bl[4][2];
            #pragma unroll
            for (int nt = 0; nt < 4; nt++) {
                u32 off = ((wn + nt * 8 + (lane & 7)) * SK + kb + ((lane >> 3) & 1) * 8) * 2;
                ldsm_x2(bh[nt], bBh + off);
                ldsm_x2(bl[nt], bBl + off);
            }
            #pragma unroll
            for (int mt = 0; mt < 4; mt++) {
                u32 off = ((wm + mt * 16 + (lane & 15)) * SK + kb + (lane >> 4) * 8) * 2;
                u32 ah[4], al[4];
                ldsm_x4(ah, bAh + off);
                ldsm_x4(al, bAl + off);
                #pragma unroll
                for (int nt = 0; nt < 4; nt++) {
                    mma_bf16(acc[mt][nt], ah, bh[nt]);
                    mma_bf16(acc[mt][nt], ah, bl[nt]);
                    mma_bf16(acc[mt][nt], al, bh[nt]);
                }
            }
        }
        __syncthreads();
    }

    // epilogue (fp32)
    #pragma unroll
    for (int mt = 0; mt < 4; mt++) {
        int m = wm + mt * 16 + ty;
        #pragma unroll
        for (int nt = 0; nt < 4; nt++) {
            int n = wn + nt * 8 + tk * 2;
            *reinterpret_cast<float2*>(&C[(size_t)m * ldc + n]) =
                make_float2(acc[mt][nt][0], acc[mt][nt][1]);
            *reinterpret_cast<float2*>(&C[(size_t)(m + 8) * ldc + n]) =
                make_float2(acc[mt][nt][2], acc[mt][nt][3]);
        }
    }
}

// ---------------------------------------------------------------------------
// Prep kernels (fp32 -> bf16 hi/lo, with transposes)
// ---------------------------------------------------------------------------
__global__ void __launch_bounds__(256) p_hid(const float* __restrict__ hidden)
{
    __shared__ float tile[64][65];
    const int tid = threadIdx.x;
    const int e0 = blockIdx.x * 64, t0 = blockIdx.y * 64, b = blockIdx.z;
    const size_t base = (size_t)b * 2048 * 1024;
    for (int i = tid; i < 4096; i += 256) {
        int r = i >> 6, c = i & 63;
        float v = hidden[base + (size_t)(t0 + r) * 1024 + e0 + c];
        tile[r][c] = v;
        u16 h, l; split2(v, h, l);
        size_t o = base + (size_t)(t0 + r) * 1024 + e0 + c;
        g_Xnh[o] = h; g_Xnl[o] = l;
    }
    __syncthreads();
    const int pair = b * 4 + (e0 >> 8), f0 = e0 & 255;
    for (int i = tid; i < 4096; i += 256) {
        int fl = i >> 6, tl = i & 63;
        u16 h, l; split2(tile[tl][fl], h, l);
        size_t o = (size_t)pair * 524288 + (size_t)(f0 + fl) * 2048 + t0 + tl;
        g_XTh[o] = h; g_XTl[o] = l;
    }
}

__global__ void __launch_bounds__(256) p_comb(const float* __restrict__ comb)
{
    __shared__ float tile[64][65];
    const int tid = threadIdx.x;
    const int g0 = blockIdx.x * 64, k0 = blockIdx.y * 64, a = blockIdx.z;
    for (int i = tid; i < 4096; i += 256) {
        int r = i >> 6, c = i & 63;
        tile[r][c] = comb[(size_t)a * 262144 + (size_t)(k0 + r) * 256 + g0 + c];
    }
    __syncthreads();
    const int q = k0 >> 8, f0 = k0 & 255;
    for (int i = tid; i < 4096; i += 256) {
        int gl = i >> 6, fl = i & 63;
        u16 h, l; split2(tile[fl][gl], h, l);
        size_t o = (size_t)(a * 4 + q) * 65536 + (size_t)(g0 + gl) * 256 + f0 + fl;
        g_CTh[o] = h; g_CTl[o] = l;
    }
}

__global__ void __launch_bounds__(256) p_q(const float* __restrict__ queries)
{
    const int i = blockIdx.x * 256 + threadIdx.x;      // 262144 float4
    float4 v = reinterpret_cast<const float4*>(queries)[i];
    ushort4 h, l;
    split2(v.x, h.x, l.x); split2(v.y, h.y, l.y);
    split2(v.z, h.z, l.z); split2(v.w, h.w, l.w);
    reinterpret_cast<ushort4*>(g_qh)[i] = h;
    reinterpret_cast<ushort4*>(g_ql)[i] = l;
}

// ---------------------------------------------------------------------------
// GEMM stages
// ---------------------------------------------------------------------------
// Gram: D[f,f'] = sum_t XT[f,t] XT[f',t]  — grid (4, 8 pairs, 8 z)
__global__ void __launch_bounds__(256, 2) k_gram()
{
    const int pair = blockIdx.y, z = blockIdx.z;
    const int m0 = (blockIdx.x >> 1) * 128, n0 = (blockIdx.x & 1) * 128;
    const u16* base_h = g_XTh + (size_t)pair * 524288;
    const u16* base_l = g_XTl + (size_t)pair * 524288;
    float* C = g_Gp + (size_t)(z * 8 + pair) * 65536 + (size_t)m0 * 256 + n0;
    gemm_ss(base_h + (size_t)m0 * 2048, base_l + (size_t)m0 * 2048, 2048,
            base_h + (size_t)n0 * 2048, base_l + (size_t)n0 * 2048, 2048,
            z * 256, z * 256 + 256, C, 256);
}

__global__ void __launch_bounds__(256) k_gred()
{
    const int i = blockIdx.x * 256 + threadIdx.x;      // 131072 float4
    const float4* P = reinterpret_cast<const float4*>(g_Gp);
    float4 s = P[i];
    #pragma unroll
    for (int z = 1; z < 8; z++) {
        float4 t = P[i + (size_t)z * 131072];
        s.x += t.x; s.y += t.y; s.z += t.z; s.w += t.w;
    }
    ushort4 h, l;
    split2(s.x, h.x, l.x); split2(s.y, h.y, l.y);
    split2(s.z, h.z, l.z); split2(s.w, h.w, l.w);
    reinterpret_cast<ushort4*>(g_Gh)[i] = h;
    reinterpret_cast<ushort4*>(g_Gl)[i] = l;
}

// B1: Tf[ba][g, q*256+f] = sum_{f'} CT[a,q][g,f'] G[b,q][f,f'] — grid (4, 32)
__global__ void __launch_bounds__(256, 2) k_b1()
{
    const int combo = blockIdx.y, q = combo & 3, ba = combo >> 2;
    const int a = ba & 3, b = ba >> 2;
    const int m0 = (blockIdx.x >> 1) * 128, n0 = (blockIdx.x & 1) * 128;
    const u16* Ah = g_CTh + (size_t)(a * 4 + q) * 65536 + (size_t)m0 * 256;
    const u16* Al = g_CTl + (size_t)(a * 4 + q) * 65536 + (size_t)m0 * 256;
    const u16* Bh = g_Gh + (size_t)(b * 4 + q) * 65536 + (size_t)n0 * 256;
    const u16* Bl = g_Gl + (size_t)(b * 4 + q) * 65536 + (size_t)n0 * 256;
    float* C = g_Tf + (size_t)ba * 262144 + (size_t)m0 * 1024 + q * 256 + n0;
    gemm_ss(Ah, Al, 256, Bh, Bl, 256, 0, 256, C, 1024);
}

__global__ void __launch_bounds__(256) k_tred()
{
    const int i = blockIdx.x * 256 + threadIdx.x;      // 524288 float4
    float4 s = reinterpret_cast<const float4*>(g_Tf)[i];
    ushort4 h, l;
    split2(s.x, h.x, l.x); split2(s.y, h.y, l.y);
    split2(s.z, h.z, l.z); split2(s.w, h.w, l.w);
    reinterpret_cast<ushort4*>(g_TTh)[i] = h;
    reinterpret_cast<ushort4*>(g_TTl)[i] = l;
}

// B2: Mt[g,e] = sum_k TT[ba][g,k] q[a][e,k] — grid (4, 8 ba, 4 z)
__global__ void __launch_bounds__(256, 2) k_b2()
{
    const int ba = blockIdx.y, z = blockIdx.z, a = ba & 3;
    const int m0 = (blockIdx.x >> 1) * 128, n0 = (blockIdx.x & 1) * 128;
    const u16* Ah = g_TTh + (size_t)ba * 262144 + (size_t)m0 * 1024;
    const u16* Al = g_TTl + (size_t)ba * 262144 + (size_t)m0 * 1024;
    const u16* Bh = g_qh + (size_t)a * 262144 + (size_t)n0 * 1024;
    const u16* Bl = g_ql + (size_t)a * 262144 + (size_t)n0 * 1024;
    float* C = g_Mp + (size_t)(z * 8 + ba) * 65536 + (size_t)m0 * 256 + n0;
    gemm_ss(Ah, Al, 1024, Bh, Bl, 1024, z * 256, z * 256 + 256, C, 256);
}

__global__ void __launch_bounds__(256) k_mred()
{
    const int i = blockIdx.x * 256 + threadIdx.x;      // 131072 float4
    const float4* P = reinterpret_cast<const float4*>(g_Mp);
    float4 s = P[i];
    #pragma unroll
    for (int z = 1; z < 4; z++) {
        float4 t = P[i + (size_t)z * 131072];
        s.x += t.x; s.y += t.y; s.z += t.z; s.w += t.w;
    }
    ushort4 h, l;
    split2(s.x, h.x, l.x); split2(s.y, h.y, l.y);
    split2(s.z, h.z, l.z); split2(s.w, h.w, l.w);
    reinterpret_cast<ushort4*>(g_Mth)[i] = h;
    reinterpret_cast<ushort4*>(g_Mtl)[i] = l;
}

// C: out[b,t,a*256+g] = sum_e Xn[b,t,a*256+e] Mt[ba][g,e] — grid (32, 8 ba)
__global__ void __launch_bounds__(256, 2) k_c(float* __restrict__ out)
{
    const int ba = blockIdx.y, b = ba >> 2, a = ba & 3;
    const int m0 = (blockIdx.x >> 1) * 128, n0 = (blockIdx.x & 1) * 128;
    const u16* Ah = g_Xnh + (size_t)b * 2097152 + (size_t)m0 * 1024 + a * 256;
    const u16* Al = g_Xnl + (size_t)b * 2097152 + (size_t)m0 * 1024 + a * 256;
    const u16* Bh = g_Mth + (size_t)ba * 65536 + (size_t)n0 * 256;
    const u16* Bl = g_Mtl + (size_t)ba * 65536 + (size_t)n0 * 256;
    float* C = out + (size_t)b * 2097152 + (size_t)m0 * 1024 + a * 256 + n0;
    gemm_ss(Ah, Al, 1024, Bh, Bl, 256, 0, 256, C, 1024);
}

// ---------------------------------------------------------------------------
extern "C" void kernel_launch(void* const* d_in, const int* in_sizes, int n_in,
                              void* d_out, int out_size)
{
    const float* hidden  = (const float*)d_in[0];   // [2, 2048, 1024]
    const float* queries = (const float*)d_in[1];   // [4, 256, 1024]
    const float* comb    = (const float*)d_in[2];   // [4, 1024, 256]
    float* out = (float*)d_out;                     // [2, 2048, 1024]

    cudaFuncSetAttribute(k_gram, cudaFuncAttributeMaxDynamicSharedMemorySize, SMEM_GEMM);
    cudaFuncSetAttribute(k_b1,   cudaFuncAttributeMaxDynamicSharedMemorySize, SMEM_GEMM);
    cudaFuncSetAttribute(k_b2,   cudaFuncAttributeMaxDynamicSharedMemorySize, SMEM_GEMM);
    cudaFuncSetAttribute(k_c,    cudaFuncAttributeMaxDynamicSharedMemorySize, SMEM_GEMM);

    p_hid <<<dim3(16, 32, 2), 256>>>(hidden);
    p_comb<<<dim3(4, 16, 4), 256>>>(comb);
    p_q   <<<1024, 256>>>(queries);
    k_gram<<<dim3(4, 8, 8), 256, SMEM_GEMM>>>();
    k_gred<<<512, 256>>>();
    k_b1  <<<dim3(4, 32), 256, SMEM_GEMM>>>();
    k_tred<<<2048, 256>>>();
    k_b2  <<<dim3(4, 8, 4), 256, SMEM_GEMM>>>();
    k_mred<<<512, 256>>>();
    k_c   <<<dim3(32, 8), 256, SMEM_GEMM>>>(out);
}